// round 2
// baseline (speedup 1.0000x reference)
#include <cuda_runtime.h>
#include <cstdint>

#define NN 23
#define IK 529            // NN*NN
#define TT 12
#define BB 16             // batches per block
#define CB 8              // batches per chunk (double-buffered)
#define NCH (BB / CB)     // 2 chunks
#define NPAIR (CB / 2)    // 4 float2 batch-pairs per chunk
#define NTHR 736          // 23 warps: warp = i, lane = k

// Batch-independent folded coefficients (recomputed every call; deterministic).
__device__ float g_att1[NN * IK];  // layout [i][m][k]
__device__ float g_att2[NN * IK];  // layout [i][m][k], diag carries residual coeff

__global__ void setup_kernel(const int* __restrict__ adj,
                             const float* __restrict__ W1,
                             const float* __restrict__ W2,
                             const float* __restrict__ a_in,
                             const float* __restrict__ a_out) {
    int i = blockIdx.x;
    int k = threadIdx.x;
    if (k >= NN) return;

    int ikidx = i * NN + k;
    float si = a_in[ikidx * 2 + 0] + a_in[ikidx * 2 + 1];
    float yi0 = a_in[ikidx * 2 + 0] / si;
    float yi1 = a_in[ikidx * 2 + 1] / si;
    float so = a_out[ikidx * 2 + 0] + a_out[ikidx * 2 + 1];
    float yo0 = a_out[ikidx * 2 + 0] / so;
    float yo1 = a_out[ikidx * 2 + 1] / so;

    float w1[NN], w2[NN], msk[NN];
    float mn1 = 1e30f, mn2 = 1e30f;
#pragma unroll
    for (int m = 0; m < NN; m++) {
        w1[m] = W1[ikidx * NN + m];
        w2[m] = W2[ikidx * NN + m];
        msk[m] = (m == k || adj[k * NN + m] != 0) ? 1.0f : 0.0f;
        mn1 = fminf(mn1, w1[m]);
        mn2 = fminf(mn2, w2[m]);
    }
    mn1 = fminf(mn1, 0.0f);   // torch.where(min > 0, 0, min)
    mn2 = fminf(mn2, 0.0f);

    float s1 = 0.0f, s2 = 0.0f;
#pragma unroll
    for (int m = 0; m < NN; m++) {
        s1 += (w1[m] - mn1) * msk[m];
        s2 += (w2[m] - mn2) * msk[m];
    }
    float sc1 = yo1 * yi0 / s1;
    float sc2 = yo1 * yi1 / s2;
#pragma unroll
    for (int m = 0; m < NN; m++) {
        g_att1[i * IK + m * NN + k] = (w1[m] - mn1) * msk[m] * sc1;
        g_att2[i * IK + m * NN + k] =
            (w2[m] - mn2) * msk[m] * sc2 + ((m == k) ? yo0 : 0.0f);
    }
}

__device__ __forceinline__ void cp_async4(void* smem_dst, const void* gmem_src) {
    uint32_t s = (uint32_t)__cvta_generic_to_shared(smem_dst);
    asm volatile("cp.async.ca.shared.global [%0], [%1], 4;\n"
                 :: "r"(s), "l"(gmem_src));
}
__device__ __forceinline__ void cp_async_commit() {
    asm volatile("cp.async.commit_group;\n" ::: "memory");
}
template <int Ngrp>
__device__ __forceinline__ void cp_async_wait() {
    asm volatile("cp.async.wait_group %0;\n" :: "n"(Ngrp) : "memory");
}

__global__ __launch_bounds__(NTHR, 1)
void resgat_kernel(const float* __restrict__ fx, float* __restrict__ out) {
    // d_s[buf][pair][ik][comp]: comp 0/1 = even/odd batch of the pair (float2)
    __shared__ __align__(16) float d_s[2][NPAIR][IK][2];

    const int tid  = threadIdx.x;
    const int wid  = tid >> 5;           // warp = i (0..22)
    const int lane = tid & 31;           // lane = k
    const int b0   = blockIdx.x * BB;

    // ---- issue chunk 0 gather (cp.async, 4B per element, stride 48B) ----
#pragma unroll
    for (int it = 0; it < 6; it++) {
        int t = tid + it * NTHR;
        if (t < CB * IK) {
            int b_l = t / IK;
            int ik  = t - b_l * IK;
            const float* src = fx + ((size_t)(b0 + b_l) * IK + ik) * TT + (TT - 1);
            cp_async4(&d_s[0][b_l >> 1][ik][b_l & 1], src);
        }
    }
    cp_async_commit();

    // ---- load folded attention rows into registers (fixed i=wid, k=lane) ----
    const int i = wid;
    const bool act = (lane < NN);
    const int k = act ? lane : 0;
    float a1[NN], a2[NN];
#pragma unroll
    for (int m = 0; m < NN; m++) {
        a1[m] = g_att1[i * IK + m * NN + k];
        a2[m] = g_att2[i * IK + m * NN + k];
    }

    for (int c = 0; c < NCH; c++) {
        int buf = c & 1;
        // issue next chunk before blocking on this one
        if (c + 1 < NCH) {
            int nb = (c + 1) & 1;
            int cb0 = b0 + (c + 1) * CB;
#pragma unroll
            for (int it = 0; it < 6; it++) {
                int t = tid + it * NTHR;
                if (t < CB * IK) {
                    int b_l = t / IK;
                    int ik  = t - b_l * IK;
                    const float* src =
                        fx + ((size_t)(cb0 + b_l) * IK + ik) * TT + (TT - 1);
                    cp_async4(&d_s[nb][b_l >> 1][ik][b_l & 1], src);
                }
            }
            cp_async_commit();
            cp_async_wait<1>();
        } else {
            cp_async_wait<0>();
        }
        __syncthreads();

        // ---- compute: out[b,i,k] = sum_m a1[m]*d[b,m,i] + a2[m]*d[b,i,m] ----
        const float* dbase = &d_s[buf][0][0][0];
#pragma unroll 1
        for (int p = 0; p < NPAIR; p++) {
            const float2* dp = (const float2*)(dbase + (size_t)p * IK * 2);
            float ax1 = 0.f, ay1 = 0.f, ax2 = 0.f, ay2 = 0.f;
#pragma unroll
            for (int m = 0; m < NN; m++) {
                float2 dc = dp[m * NN + i];   // d[b, m, i] (uniform addr: broadcast)
                float2 dr = dp[i * NN + m];   // d[b, i, m]
                ax1 += a1[m] * dc.x;
                ay1 += a1[m] * dc.y;
                ax2 += a2[m] * dr.x;
                ay2 += a2[m] * dr.y;
            }
            if (act) {
                int b = b0 + c * CB + 2 * p;
                out[(size_t)b * IK + i * NN + k]       = ax1 + ax2;
                out[(size_t)(b + 1) * IK + i * NN + k] = ay1 + ay2;
            }
        }
        __syncthreads();
    }
}

extern "C" void kernel_launch(void* const* d_in, const int* in_sizes, int n_in,
                              void* d_out, int out_size) {
    const float* fx    = (const float*)d_in[0];
    const int*   adj   = (const int*)d_in[1];
    const float* W1    = (const float*)d_in[2];
    const float* W2    = (const float*)d_in[3];
    const float* a_in  = (const float*)d_in[4];
    const float* a_out = (const float*)d_in[5];
    float* out = (float*)d_out;

    setup_kernel<<<NN, 32>>>(adj, W1, W2, a_in, a_out);

    int B = in_sizes[0] / (IK * TT);   // 8192
    resgat_kernel<<<B / BB, NTHR>>>(fx, out);
}